// round 4
// baseline (speedup 1.0000x reference)
#include <cuda_runtime.h>
#include <cuda_bf16.h>
#include <math.h>

// Problem constants
#define BATCH 16384
#define DIM   768
#define NK    4
#define H1    512
#define H2    256

// ---------------------------------------------------------------------------
// Scratch (device globals -- no allocation allowed)
// ---------------------------------------------------------------------------
__device__ float g_buf1[BATCH * H1];          // emb@W1+b1 -> in-place LN+ReLU -> h1
__device__ float g_buf2[BATCH * H2];          // h1@W2+b2  -> in-place LN+ReLU -> h2
__device__ float g_logits[BATCH * DIM];       // h2@Wa+ba (pre-softmax)
__device__ float g_wflat[BATCH * NK * DIM];   // h2@Wd+bd

// ---------------------------------------------------------------------------
// Block reduction helpers (blockDim.x == 256)
// ---------------------------------------------------------------------------
__device__ __forceinline__ float block_sum(float val) {
    __shared__ float sh[32];
    int lane = threadIdx.x & 31;
    int wid  = threadIdx.x >> 5;
    #pragma unroll
    for (int o = 16; o > 0; o >>= 1) val += __shfl_xor_sync(0xFFFFFFFFu, val, o);
    if (lane == 0) sh[wid] = val;
    __syncthreads();
    int nw = blockDim.x >> 5;
    val = (threadIdx.x < nw) ? sh[threadIdx.x] : 0.0f;
    if (wid == 0) {
        #pragma unroll
        for (int o = 16; o > 0; o >>= 1) val += __shfl_xor_sync(0xFFFFFFFFu, val, o);
        if (lane == 0) sh[0] = val;
    }
    __syncthreads();
    val = sh[0];
    __syncthreads();
    return val;
}

__device__ __forceinline__ float block_max(float val) {
    __shared__ float sh[32];
    int lane = threadIdx.x & 31;
    int wid  = threadIdx.x >> 5;
    #pragma unroll
    for (int o = 16; o > 0; o >>= 1) val = fmaxf(val, __shfl_xor_sync(0xFFFFFFFFu, val, o));
    if (lane == 0) sh[wid] = val;
    __syncthreads();
    int nw = blockDim.x >> 5;
    val = (threadIdx.x < nw) ? sh[threadIdx.x] : -INFINITY;
    if (wid == 0) {
        #pragma unroll
        for (int o = 16; o > 0; o >>= 1) val = fmaxf(val, __shfl_xor_sync(0xFFFFFFFFu, val, o));
        if (lane == 0) sh[0] = val;
    }
    __syncthreads();
    val = sh[0];
    __syncthreads();
    return val;
}

// ---------------------------------------------------------------------------
// SGEMM: C[M,N] = A[M,K] * B[K,N] + bias[N]
// BM=BN=128, BK=16, 256 threads, 8x8 per-thread microtile.
// Double-buffered shared memory; global loads of slab t+1 overlap compute of t.
// Requires M%128==0, N%128==0, K%16==0 (true here: K=768,512,256).
// ---------------------------------------------------------------------------
#define GBM 128
#define GBN 128
#define GBK 16
#define GTM 8
#define GTN 8

__global__ __launch_bounds__(256) void sgemm_bias_kernel(
    int M, int N, int Kd,
    const float* __restrict__ A,
    const float* __restrict__ Bm,
    const float* __restrict__ bias,
    float* __restrict__ C)
{
    // As stored transposed: As[buf][k][m]; Bs natural: Bs[buf][k][n]
    __shared__ float As[2][GBK][GBM];
    __shared__ float Bs[2][GBK][GBN];

    const int bx = blockIdx.x;   // N tile
    const int by = blockIdx.y;   // M tile
    const int tid = threadIdx.x;

    const int tcol = tid & 15;   // 0..15  (N dir, *GTN)
    const int trow = tid >> 4;   // 0..15  (M dir, *GTM)

    // A tile: 128 rows x 16 cols = 512 float4; thread handles f = tid, tid+256.
    // B tile: 16 rows x 128 cols = 512 float4; same split.
    const int a0Row = tid >> 2,            a0Col = (tid & 3) * 4;
    const int a1Row = (tid + 256) >> 2,    a1Col = ((tid + 256) & 3) * 4;
    const int b0Row = tid >> 5,            b0Col = (tid & 31) * 4;
    const int b1Row = (tid + 256) >> 5,    b1Col = ((tid + 256) & 31) * 4;

    const float* Aptr = A + (size_t)(by * GBM) * Kd;
    const float* Bptr = Bm + (size_t)(bx * GBN);

    float acc[GTM][GTN];
    #pragma unroll
    for (int i = 0; i < GTM; i++)
        #pragma unroll
        for (int j = 0; j < GTN; j++) acc[i][j] = 0.0f;

    const int ntiles = Kd / GBK;

    // ---- preload slab 0 into buffer 0 ----
    {
        float4 a0 = *(const float4*)(Aptr + (size_t)a0Row * Kd + a0Col);
        float4 a1 = *(const float4*)(Aptr + (size_t)a1Row * Kd + a1Col);
        float4 bv0 = *(const float4*)(Bptr + (size_t)b0Row * N + b0Col);
        float4 bv1 = *(const float4*)(Bptr + (size_t)b1Row * N + b1Col);
        As[0][a0Col + 0][a0Row] = a0.x;  As[0][a0Col + 1][a0Row] = a0.y;
        As[0][a0Col + 2][a0Row] = a0.z;  As[0][a0Col + 3][a0Row] = a0.w;
        As[0][a1Col + 0][a1Row] = a1.x;  As[0][a1Col + 1][a1Row] = a1.y;
        As[0][a1Col + 2][a1Row] = a1.z;  As[0][a1Col + 3][a1Row] = a1.w;
        *(float4*)&Bs[0][b0Row][b0Col] = bv0;
        *(float4*)&Bs[0][b1Row][b1Col] = bv1;
    }
    __syncthreads();

    float regA[GTM], regB[GTN];

    for (int t = 0; t < ntiles; t++) {
        const int cur = t & 1;
        const int nxt = cur ^ 1;

        // ---- prefetch slab t+1 from global into registers ----
        float4 pa0, pa1, pb0, pb1;
        const bool more = (t + 1 < ntiles);
        if (more) {
            const int k0 = (t + 1) * GBK;
            pa0 = *(const float4*)(Aptr + (size_t)a0Row * Kd + k0 + a0Col);
            pa1 = *(const float4*)(Aptr + (size_t)a1Row * Kd + k0 + a1Col);
            pb0 = *(const float4*)(Bptr + (size_t)(k0 + b0Row) * N + b0Col);
            pb1 = *(const float4*)(Bptr + (size_t)(k0 + b1Row) * N + b1Col);
        }

        // ---- compute current slab ----
        #pragma unroll
        for (int kk = 0; kk < GBK; kk++) {
            #pragma unroll
            for (int i = 0; i < GTM; i++) regA[i] = As[cur][kk][trow * GTM + i];
            #pragma unroll
            for (int j = 0; j < GTN; j++) regB[j] = Bs[cur][kk][tcol * GTN + j];
            #pragma unroll
            for (int i = 0; i < GTM; i++)
                #pragma unroll
                for (int j = 0; j < GTN; j++)
                    acc[i][j] = fmaf(regA[i], regB[j], acc[i][j]);
        }

        // ---- store prefetched slab into the other buffer ----
        if (more) {
            As[nxt][a0Col + 0][a0Row] = pa0.x;  As[nxt][a0Col + 1][a0Row] = pa0.y;
            As[nxt][a0Col + 2][a0Row] = pa0.z;  As[nxt][a0Col + 3][a0Row] = pa0.w;
            As[nxt][a1Col + 0][a1Row] = pa1.x;  As[nxt][a1Col + 1][a1Row] = pa1.y;
            As[nxt][a1Col + 2][a1Row] = pa1.z;  As[nxt][a1Col + 3][a1Row] = pa1.w;
            *(float4*)&Bs[nxt][b0Row][b0Col] = pb0;
            *(float4*)&Bs[nxt][b1Row][b1Col] = pb1;
            __syncthreads();
        }
    }

    // epilogue: add per-column bias, store
    const int ncol0 = bx * GBN + tcol * GTN;
    float bv[GTN];
    #pragma unroll
    for (int j = 0; j < GTN; j++) bv[j] = bias[ncol0 + j];

    #pragma unroll
    for (int i = 0; i < GTM; i++) {
        const int row = by * GBM + trow * GTM + i;
        float* crow = C + (size_t)row * N + ncol0;
        float4 o0 = make_float4(acc[i][0] + bv[0], acc[i][1] + bv[1],
                                acc[i][2] + bv[2], acc[i][3] + bv[3]);
        float4 o1 = make_float4(acc[i][4] + bv[4], acc[i][5] + bv[5],
                                acc[i][6] + bv[6], acc[i][7] + bv[7]);
        *(float4*)(crow + 0) = o0;
        *(float4*)(crow + 4) = o1;
    }
}

// ---------------------------------------------------------------------------
// In-place LayerNorm + ReLU over rows of width W. blockDim = 256, grid = BATCH.
// ---------------------------------------------------------------------------
template<int W>
__global__ __launch_bounds__(256) void ln_relu_kernel(
    float* __restrict__ X,
    const float* __restrict__ g,
    const float* __restrict__ b)
{
    constexpr int PT = W / 256;
    const int row = blockIdx.x;
    const int tid = threadIdx.x;
    float* x = X + (size_t)row * W;

    float v[PT];
    float s = 0.0f, s2 = 0.0f;
    #pragma unroll
    for (int i = 0; i < PT; i++) {
        v[i] = x[i * 256 + tid];
        s  += v[i];
        s2 += v[i] * v[i];
    }
    s  = block_sum(s);
    s2 = block_sum(s2);
    const float mu  = s * (1.0f / W);
    const float var = fmaxf(s2 * (1.0f / W) - mu * mu, 0.0f);
    const float rs  = rsqrtf(var + 1e-5f);

    #pragma unroll
    for (int i = 0; i < PT; i++) {
        const int c = i * 256 + tid;
        float y = (v[i] - mu) * rs * g[c] + b[c];
        x[c] = fmaxf(y, 0.0f);
    }
}

// ---------------------------------------------------------------------------
// Fused: softmax(logits) -> out_attn, then scale wflat by attn and run
// Gram-Schmidt over K=4 vectors of dim 768 per row -> out_w.
// blockDim = 256 (3 elems/thread/vector), grid = BATCH.
// ---------------------------------------------------------------------------
__global__ __launch_bounds__(256) void softmax_attn_gs_kernel(
    const float* __restrict__ logits,
    const float* __restrict__ wflat,
    float* __restrict__ out_attn,
    float* __restrict__ out_w)
{
    constexpr int PT = DIM / 256;   // 3
    const int row = blockIdx.x;
    const int tid = threadIdx.x;

    // ---- softmax over logits row ----
    const float* x = logits + (size_t)row * DIM;
    float av[PT];
    float m = -INFINITY;
    #pragma unroll
    for (int i = 0; i < PT; i++) {
        av[i] = x[i * 256 + tid];
        m = fmaxf(m, av[i]);
    }
    m = block_max(m);
    float s = 0.0f;
    #pragma unroll
    for (int i = 0; i < PT; i++) {
        av[i] = __expf(av[i] - m);
        s += av[i];
    }
    s = block_sum(s);
    const float invs = 1.0f / s;
    #pragma unroll
    for (int i = 0; i < PT; i++) {
        av[i] *= invs;
        out_attn[(size_t)row * DIM + i * 256 + tid] = av[i];
    }

    // ---- scale W rows by attn ----
    float v[NK][PT];
    #pragma unroll
    for (int k = 0; k < NK; k++)
        #pragma unroll
        for (int i = 0; i < PT; i++)
            v[k][i] = wflat[(size_t)row * (NK * DIM) + k * DIM + i * 256 + tid] * av[i];

    // ---- Gram-Schmidt, same order as reference ----
    #pragma unroll
    for (int k = 0; k < NK; k++) {
        for (int j = 0; j < k; j++) {
            float p = 0.0f;
            #pragma unroll
            for (int i = 0; i < PT; i++) p += v[k][i] * v[j][i];
            p = block_sum(p);
            #pragma unroll
            for (int i = 0; i < PT; i++) v[k][i] -= p * v[j][i];
        }
        float nn = 0.0f;
        #pragma unroll
        for (int i = 0; i < PT; i++) nn += v[k][i] * v[k][i];
        nn = block_sum(nn);
        const float inv = 1.0f / fmaxf(sqrtf(nn), 1e-12f);
        #pragma unroll
        for (int i = 0; i < PT; i++) {
            v[k][i] *= inv;
            out_w[(size_t)row * (NK * DIM) + k * DIM + i * 256 + tid] = v[k][i];
        }
    }
}

// ---------------------------------------------------------------------------
// Launch
// Inputs (metadata order = reference signature order):
//  0 embeddings [B,768]  1 W1[768,512]  2 b1[512]  3 g1[512]  4 be1[512]
//  5 W2[512,256]  6 b2[256]  7 g2[256]  8 be2[256]
//  9 Wd[256,3072] 10 bd[3072] 11 Wa[256,768] 12 ba[768]
// Output: W_ortho [B,4,768] followed by attn [B,768]  (concatenated fp32)
// ---------------------------------------------------------------------------
extern "C" void kernel_launch(void* const* d_in, const int* in_sizes, int n_in,
                              void* d_out, int out_size)
{
    const float* emb = (const float*)d_in[0];
    const float* W1  = (const float*)d_in[1];
    const float* b1  = (const float*)d_in[2];
    const float* g1  = (const float*)d_in[3];
    const float* be1 = (const float*)d_in[4];
    const float* W2  = (const float*)d_in[5];
    const float* b2  = (const float*)d_in[6];
    const float* g2  = (const float*)d_in[7];
    const float* be2 = (const float*)d_in[8];
    const float* Wd  = (const float*)d_in[9];
    const float* bd  = (const float*)d_in[10];
    const float* Wa  = (const float*)d_in[11];
    const float* ba  = (const float*)d_in[12];

    float* out_w    = (float*)d_out;                            // [B, 4, 768]
    float* out_attn = (float*)d_out + (size_t)BATCH * NK * DIM; // [B, 768]

    float *buf1, *buf2, *logits, *wflat;
    cudaGetSymbolAddress((void**)&buf1,   g_buf1);
    cudaGetSymbolAddress((void**)&buf2,   g_buf2);
    cudaGetSymbolAddress((void**)&logits, g_logits);
    cudaGetSymbolAddress((void**)&wflat,  g_wflat);

    dim3 blk(256);

    // 1) buf1 = emb @ W1 + b1   [16384, 512]
    sgemm_bias_kernel<<<dim3(H1 / GBN, BATCH / GBM), blk>>>(BATCH, H1, DIM, emb, W1, b1, buf1);
    // 2) LN + ReLU in-place -> h1
    ln_relu_kernel<H1><<<BATCH, blk>>>(buf1, g1, be1);
    // 3) buf2 = h1 @ W2 + b2    [16384, 256]
    sgemm_bias_kernel<<<dim3(H2 / GBN, BATCH / GBM), blk>>>(BATCH, H2, H1, buf1, W2, b2, buf2);
    // 4) LN + ReLU in-place -> h2
    ln_relu_kernel<H2><<<BATCH, blk>>>(buf2, g2, be2);
    // 5) logits = h2 @ Wa + ba  [16384, 768]
    sgemm_bias_kernel<<<dim3(DIM / GBN, BATCH / GBM), blk>>>(BATCH, DIM, H2, buf2, Wa, ba, logits);
    // 6) wflat = h2 @ Wd + bd   [16384, 3072]
    sgemm_bias_kernel<<<dim3((NK * DIM) / GBN, BATCH / GBM), blk>>>(BATCH, NK * DIM, H2, buf2, Wd, bd, wflat);
    // 7) fused softmax + attn-scale + Gram-Schmidt -> out_attn, out_w
    softmax_attn_gs_kernel<<<BATCH, blk>>>(logits, wflat, out_attn, out_w);
}

// round 5
// speedup vs baseline: 1.8697x; 1.8697x over previous
#include <cuda_runtime.h>
#include <cuda_bf16.h>
#include <math.h>
#include <stdint.h>

// Problem constants
#define BATCH 16384
#define DIM   768
#define NK    4
#define H1    512
#define H2    256

// ---------------------------------------------------------------------------
// Scratch (device globals -- no allocation allowed)
// ---------------------------------------------------------------------------
__device__ float g_buf1[BATCH * H1];          // emb@W1+b1 -> in-place LN+ReLU -> h1
__device__ float g_buf2[BATCH * H2];          // h1@W2+b2  -> in-place LN+ReLU -> h2
__device__ float g_logits[BATCH * DIM];       // h2@Wa+ba (pre-softmax)
__device__ float g_wflat[BATCH * NK * DIM];   // h2@Wd+bd

// ---------------------------------------------------------------------------
// Block reduction helpers (blockDim.x == 256)
// ---------------------------------------------------------------------------
__device__ __forceinline__ float block_sum(float val) {
    __shared__ float sh[32];
    int lane = threadIdx.x & 31;
    int wid  = threadIdx.x >> 5;
    #pragma unroll
    for (int o = 16; o > 0; o >>= 1) val += __shfl_xor_sync(0xFFFFFFFFu, val, o);
    if (lane == 0) sh[wid] = val;
    __syncthreads();
    int nw = blockDim.x >> 5;
    val = (threadIdx.x < nw) ? sh[threadIdx.x] : 0.0f;
    if (wid == 0) {
        #pragma unroll
        for (int o = 16; o > 0; o >>= 1) val += __shfl_xor_sync(0xFFFFFFFFu, val, o);
        if (lane == 0) sh[0] = val;
    }
    __syncthreads();
    val = sh[0];
    __syncthreads();
    return val;
}

__device__ __forceinline__ float block_max(float val) {
    __shared__ float sh[32];
    int lane = threadIdx.x & 31;
    int wid  = threadIdx.x >> 5;
    #pragma unroll
    for (int o = 16; o > 0; o >>= 1) val = fmaxf(val, __shfl_xor_sync(0xFFFFFFFFu, val, o));
    if (lane == 0) sh[wid] = val;
    __syncthreads();
    int nw = blockDim.x >> 5;
    val = (threadIdx.x < nw) ? sh[threadIdx.x] : -INFINITY;
    if (wid == 0) {
        #pragma unroll
        for (int o = 16; o > 0; o >>= 1) val = fmaxf(val, __shfl_xor_sync(0xFFFFFFFFu, val, o));
        if (lane == 0) sh[0] = val;
    }
    __syncthreads();
    val = sh[0];
    __syncthreads();
    return val;
}

// ---------------------------------------------------------------------------
// tf32 helpers
// ---------------------------------------------------------------------------
__device__ __forceinline__ uint32_t f2tf32(float f) {
    uint32_t u;
    asm("cvt.rna.tf32.f32 %0, %1;" : "=r"(u) : "f"(f));
    return u;
}

__device__ __forceinline__ void mma_tf32(
    float& c0, float& c1, float& c2, float& c3,
    uint32_t a0, uint32_t a1, uint32_t a2, uint32_t a3,
    uint32_t b0, uint32_t b1)
{
    asm volatile(
        "mma.sync.aligned.m16n8k8.row.col.f32.tf32.tf32.f32 "
        "{%0,%1,%2,%3}, {%4,%5,%6,%7}, {%8,%9}, {%0,%1,%2,%3};"
        : "+f"(c0), "+f"(c1), "+f"(c2), "+f"(c3)
        : "r"(a0), "r"(a1), "r"(a2), "r"(a3), "r"(b0), "r"(b1));
}

// ---------------------------------------------------------------------------
// tf32 tensor-core GEMM: C[M,N] = A[M,K] * B[K,N] + bias[N]
// Block tile 128x128, BK=16, 256 threads (8 warps, 2x4 grid, 64x32 per warp).
// mma.sync m16n8k8 tf32; fp32 accumulate. Double-buffered SMEM + reg prefetch.
// SMEM padding chosen so all fragment LDS patterns are bank-conflict-free:
//   A stride 20:  bank=(20m+k)%32 distinct over (g=0..7, t=0..3)
//   B stride 136: bank=(8k+n)%32  distinct over (t=0..3, g=0..7)
// Requires M%128==0, N%128==0, K%16==0 (true here: K=768,512,256).
// ---------------------------------------------------------------------------
#define TBM 128
#define TBN 128
#define TBK 16
#define APAD 4     // A row stride = TBK+APAD = 20
#define BPAD 8     // B row stride = TBN+BPAD = 136

__global__ __launch_bounds__(256, 1) void tf32_gemm_bias_kernel(
    int M, int N, int Kd,
    const float* __restrict__ A,
    const float* __restrict__ Bm,
    const float* __restrict__ bias,
    float* __restrict__ C)
{
    __shared__ uint32_t As[2][TBM][TBK + APAD];   // tf32 bits, [m][k]
    __shared__ uint32_t Bs[2][TBK][TBN + BPAD];   // tf32 bits, [k][n]

    const int bx = blockIdx.x;    // N tile
    const int by = blockIdx.y;    // M tile
    const int tid = threadIdx.x;
    const int w   = tid >> 5;     // warp 0..7
    const int lane = tid & 31;
    const int g = lane >> 2;      // groupID 0..7
    const int t = lane & 3;       // threadID_in_group 0..3
    const int wm = w >> 2;        // 0..1  -> m offset wm*64
    const int wn = w & 3;         // 0..3  -> n offset wn*32

    // Global->SMEM tiling: A tile 128x16 = 512 float4, B tile 16x128 = 512 float4.
    // 256 threads, 2 float4 each per tile.
    const int a0Row = tid >> 2,         a0Col = (tid & 3) * 4;
    const int a1Row = (tid + 256) >> 2, a1Col = ((tid + 256) & 3) * 4;
    const int b0Row = tid >> 5,         b0Col = (tid & 31) * 4;
    const int b1Row = (tid + 256) >> 5, b1Col = ((tid + 256) & 31) * 4;

    const float* Aptr = A + (size_t)(by * TBM) * Kd;
    const float* Bptr = Bm + (size_t)(bx * TBN);

    float acc[4][4][4];   // [mi][ni][c0..c3]
    #pragma unroll
    for (int mi = 0; mi < 4; mi++)
        #pragma unroll
        for (int ni = 0; ni < 4; ni++)
            #pragma unroll
            for (int c = 0; c < 4; c++) acc[mi][ni][c] = 0.0f;

    const int ntiles = Kd / TBK;

    // ---- preload slab 0 into buffer 0 (convert to tf32 at store) ----
    {
        float4 a0 = *(const float4*)(Aptr + (size_t)a0Row * Kd + a0Col);
        float4 a1 = *(const float4*)(Aptr + (size_t)a1Row * Kd + a1Col);
        float4 bv0 = *(const float4*)(Bptr + (size_t)b0Row * N + b0Col);
        float4 bv1 = *(const float4*)(Bptr + (size_t)b1Row * N + b1Col);
        As[0][a0Row][a0Col + 0] = f2tf32(a0.x);  As[0][a0Row][a0Col + 1] = f2tf32(a0.y);
        As[0][a0Row][a0Col + 2] = f2tf32(a0.z);  As[0][a0Row][a0Col + 3] = f2tf32(a0.w);
        As[0][a1Row][a1Col + 0] = f2tf32(a1.x);  As[0][a1Row][a1Col + 1] = f2tf32(a1.y);
        As[0][a1Row][a1Col + 2] = f2tf32(a1.z);  As[0][a1Row][a1Col + 3] = f2tf32(a1.w);
        Bs[0][b0Row][b0Col + 0] = f2tf32(bv0.x); Bs[0][b0Row][b0Col + 1] = f2tf32(bv0.y);
        Bs[0][b0Row][b0Col + 2] = f2tf32(bv0.z); Bs[0][b0Row][b0Col + 3] = f2tf32(bv0.w);
        Bs[0][b1Row][b1Col + 0] = f2tf32(bv1.x); Bs[0][b1Row][b1Col + 1] = f2tf32(bv1.y);
        Bs[0][b1Row][b1Col + 2] = f2tf32(bv1.z); Bs[0][b1Row][b1Col + 3] = f2tf32(bv1.w);
    }
    __syncthreads();

    for (int tt = 0; tt < ntiles; tt++) {
        const int cur = tt & 1;
        const int nxt = cur ^ 1;

        // ---- prefetch slab tt+1 into registers ----
        float4 pa0, pa1, pb0, pb1;
        const bool more = (tt + 1 < ntiles);
        if (more) {
            const int k0 = (tt + 1) * TBK;
            pa0 = *(const float4*)(Aptr + (size_t)a0Row * Kd + k0 + a0Col);
            pa1 = *(const float4*)(Aptr + (size_t)a1Row * Kd + k0 + a1Col);
            pb0 = *(const float4*)(Bptr + (size_t)(k0 + b0Row) * N + b0Col);
            pb1 = *(const float4*)(Bptr + (size_t)(k0 + b1Row) * N + b1Col);
        }

        // ---- compute current slab: 2 k-steps of 8 ----
        #pragma unroll
        for (int ks = 0; ks < 2; ks++) {
            const int kb = ks * 8;
            uint32_t af[4][4];
            uint32_t bf[4][2];
            #pragma unroll
            for (int mi = 0; mi < 4; mi++) {
                const int r0 = wm * 64 + mi * 16 + g;
                af[mi][0] = As[cur][r0    ][kb + t];
                af[mi][1] = As[cur][r0 + 8][kb + t];
                af[mi][2] = As[cur][r0    ][kb + t + 4];
                af[mi][3] = As[cur][r0 + 8][kb + t + 4];
            }
            #pragma unroll
            for (int ni = 0; ni < 4; ni++) {
                const int cN = wn * 32 + ni * 8 + g;
                bf[ni][0] = Bs[cur][kb + t    ][cN];
                bf[ni][1] = Bs[cur][kb + t + 4][cN];
            }
            #pragma unroll
            for (int mi = 0; mi < 4; mi++)
                #pragma unroll
                for (int ni = 0; ni < 4; ni++)
                    mma_tf32(acc[mi][ni][0], acc[mi][ni][1], acc[mi][ni][2], acc[mi][ni][3],
                             af[mi][0], af[mi][1], af[mi][2], af[mi][3],
                             bf[ni][0], bf[ni][1]);
        }

        // ---- store prefetched slab into the other buffer ----
        if (more) {
            As[nxt][a0Row][a0Col + 0] = f2tf32(pa0.x);  As[nxt][a0Row][a0Col + 1] = f2tf32(pa0.y);
            As[nxt][a0Row][a0Col + 2] = f2tf32(pa0.z);  As[nxt][a0Row][a0Col + 3] = f2tf32(pa0.w);
            As[nxt][a1Row][a1Col + 0] = f2tf32(pa1.x);  As[nxt][a1Row][a1Col + 1] = f2tf32(pa1.y);
            As[nxt][a1Row][a1Col + 2] = f2tf32(pa1.z);  As[nxt][a1Row][a1Col + 3] = f2tf32(pa1.w);
            Bs[nxt][b0Row][b0Col + 0] = f2tf32(pb0.x);  Bs[nxt][b0Row][b0Col + 1] = f2tf32(pb0.y);
            Bs[nxt][b0Row][b0Col + 2] = f2tf32(pb0.z);  Bs[nxt][b0Row][b0Col + 3] = f2tf32(pb0.w);
            Bs[nxt][b1Row][b1Col + 0] = f2tf32(pb1.x);  Bs[nxt][b1Row][b1Col + 1] = f2tf32(pb1.y);
            Bs[nxt][b1Row][b1Col + 2] = f2tf32(pb1.z);  Bs[nxt][b1Row][b1Col + 3] = f2tf32(pb1.w);
        }
        __syncthreads();
    }

    // ---- epilogue: bias add + store ----
    #pragma unroll
    for (int mi = 0; mi < 4; mi++) {
        const int r0 = by * TBM + wm * 64 + mi * 16 + g;
        #pragma unroll
        for (int ni = 0; ni < 4; ni++) {
            const int cN = bx * TBN + wn * 32 + ni * 8 + t * 2;
            const float bz0 = bias[cN], bz1 = bias[cN + 1];
            float2 v0 = make_float2(acc[mi][ni][0] + bz0, acc[mi][ni][1] + bz1);
            float2 v1 = make_float2(acc[mi][ni][2] + bz0, acc[mi][ni][3] + bz1);
            *(float2*)(C + (size_t)r0 * N + cN)       = v0;
            *(float2*)(C + (size_t)(r0 + 8) * N + cN) = v1;
        }
    }
}

// ---------------------------------------------------------------------------
// In-place LayerNorm + ReLU over rows of width W. blockDim = 256, grid = BATCH.
// ---------------------------------------------------------------------------
template<int W>
__global__ __launch_bounds__(256) void ln_relu_kernel(
    float* __restrict__ X,
    const float* __restrict__ g,
    const float* __restrict__ b)
{
    constexpr int PT = W / 256;
    const int row = blockIdx.x;
    const int tid = threadIdx.x;
    float* x = X + (size_t)row * W;

    float v[PT];
    float s = 0.0f, s2 = 0.0f;
    #pragma unroll
    for (int i = 0; i < PT; i++) {
        v[i] = x[i * 256 + tid];
        s  += v[i];
        s2 += v[i] * v[i];
    }
    s  = block_sum(s);
    s2 = block_sum(s2);
    const float mu  = s * (1.0f / W);
    const float var = fmaxf(s2 * (1.0f / W) - mu * mu, 0.0f);
    const float rs  = rsqrtf(var + 1e-5f);

    #pragma unroll
    for (int i = 0; i < PT; i++) {
        const int c = i * 256 + tid;
        float y = (v[i] - mu) * rs * g[c] + b[c];
        x[c] = fmaxf(y, 0.0f);
    }
}

// ---------------------------------------------------------------------------
// Fused: softmax(logits) -> out_attn, then scale wflat by attn and run
// Gram-Schmidt over K=4 vectors of dim 768 per row -> out_w.
// blockDim = 256 (3 elems/thread/vector), grid = BATCH.
// ---------------------------------------------------------------------------
__global__ __launch_bounds__(256) void softmax_attn_gs_kernel(
    const float* __restrict__ logits,
    const float* __restrict__ wflat,
    float* __restrict__ out_attn,
    float* __restrict__ out_w)
{
    constexpr int PT = DIM / 256;   // 3
    const int row = blockIdx.x;
    const int tid = threadIdx.x;

    // ---- softmax over logits row ----
    const float* x = logits + (size_t)row * DIM;
    float av[PT];
    float m = -INFINITY;
    #pragma unroll
    for (int i = 0; i < PT; i++) {
        av[i] = x[i * 256 + tid];
        m = fmaxf(m, av[i]);
    }
    m = block_max(m);
    float s = 0.0f;
    #pragma unroll
    for (int i = 0; i < PT; i++) {
        av[i] = __expf(av[i] - m);
        s += av[i];
    }
    s = block_sum(s);
    const float invs = 1.0f / s;
    #pragma unroll
    for (int i = 0; i < PT; i++) {
        av[i] *= invs;
        out_attn[(size_t)row * DIM + i * 256 + tid] = av[i];
    }

    // ---- scale W rows by attn ----
    float v[NK][PT];
    #pragma unroll
    for (int k = 0; k < NK; k++)
        #pragma unroll
        for (int i = 0; i < PT; i++)
            v[k][i] = wflat[(size_t)row * (NK * DIM) + k * DIM + i * 256 + tid] * av[i];

    // ---- Gram-Schmidt, same order as reference ----
    #pragma unroll
    for (int k = 0; k < NK; k++) {
        for (int j = 0; j < k; j++) {
            float p = 0.0f;
            #pragma unroll
            for (int i = 0; i < PT; i++) p += v[k][i] * v[j][i];
            p = block_sum(p);
            #pragma unroll
            for (int i = 0; i < PT; i++) v[k][i] -= p * v[j][i];
        }
        float nn = 0.0f;
        #pragma unroll
        for (int i = 0; i < PT; i++) nn += v[k][i] * v[k][i];
        nn = block_sum(nn);
        const float inv = 1.0f / fmaxf(sqrtf(nn), 1e-12f);
        #pragma unroll
        for (int i = 0; i < PT; i++) {
            v[k][i] *= inv;
            out_w[(size_t)row * (NK * DIM) + k * DIM + i * 256 + tid] = v[k][i];
        }
    }
}

// ---------------------------------------------------------------------------
// Launch
// Inputs (metadata order = reference signature order):
//  0 embeddings [B,768]  1 W1[768,512]  2 b1[512]  3 g1[512]  4 be1[512]
//  5 W2[512,256]  6 b2[256]  7 g2[256]  8 be2[256]
//  9 Wd[256,3072] 10 bd[3072] 11 Wa[256,768] 12 ba[768]
// Output: W_ortho [B,4,768] followed by attn [B,768]  (concatenated fp32)
// ---------------------------------------------------------------------------
extern "C" void kernel_launch(void* const* d_in, const int* in_sizes, int n_in,
                              void* d_out, int out_size)
{
    const float* emb = (const float*)d_in[0];
    const float* W1  = (const float*)d_in[1];
    const float* b1  = (const float*)d_in[2];
    const float* g1  = (const float*)d_in[3];
    const float* be1 = (const float*)d_in[4];
    const float* W2  = (const float*)d_in[5];
    const float* b2  = (const float*)d_in[6];
    const float* g2  = (const float*)d_in[7];
    const float* be2 = (const float*)d_in[8];
    const float* Wd  = (const float*)d_in[9];
    const float* bd  = (const float*)d_in[10];
    const float* Wa  = (const float*)d_in[11];
    const float* ba  = (const float*)d_in[12];

    float* out_w    = (float*)d_out;                            // [B, 4, 768]
    float* out_attn = (float*)d_out + (size_t)BATCH * NK * DIM; // [B, 768]

    float *buf1, *buf2, *logits, *wflat;
    cudaGetSymbolAddress((void**)&buf1,   g_buf1);
    cudaGetSymbolAddress((void**)&buf2,   g_buf2);
    cudaGetSymbolAddress((void**)&logits, g_logits);
    cudaGetSymbolAddress((void**)&wflat,  g_wflat);

    dim3 blk(256);

    // 1) buf1 = emb @ W1 + b1   [16384, 512]
    tf32_gemm_bias_kernel<<<dim3(H1 / TBN, BATCH / TBM), blk>>>(BATCH, H1, DIM, emb, W1, b1, buf1);
    // 2) LN + ReLU in-place -> h1
    ln_relu_kernel<H1><<<BATCH, blk>>>(buf1, g1, be1);
    // 3) buf2 = h1 @ W2 + b2    [16384, 256]
    tf32_gemm_bias_kernel<<<dim3(H2 / TBN, BATCH / TBM), blk>>>(BATCH, H2, H1, buf1, W2, b2, buf2);
    // 4) LN + ReLU in-place -> h2
    ln_relu_kernel<H2><<<BATCH, blk>>>(buf2, g2, be2);
    // 5) logits = h2 @ Wa + ba  [16384, 768]
    tf32_gemm_bias_kernel<<<dim3(DIM / TBN, BATCH / TBM), blk>>>(BATCH, DIM, H2, buf2, Wa, ba, logits);
    // 6) wflat = h2 @ Wd + bd   [16384, 3072]
    tf32_gemm_bias_kernel<<<dim3((NK * DIM) / TBN, BATCH / TBM), blk>>>(BATCH, NK * DIM, H2, buf2, Wd, bd, wflat);
    // 7) fused softmax + attn-scale + Gram-Schmidt -> out_attn, out_w
    softmax_attn_gs_kernel<<<BATCH, blk>>>(logits, wflat, out_attn, out_w);
}